// round 12
// baseline (speedup 1.0000x reference)
#include <cuda_runtime.h>
#include <cuda_fp16.h>
#include <cuda_bf16.h>

#define N_NODES 100000
#define N_EDGES 1600000
#define D_IN    128
#define D_OUT   64
#define SCAN_BLK 1024
#define NBLK ((N_NODES + SCAN_BLK - 1) / SCAN_BLK)   // 98

#define GEMM_BLOCKS ((N_NODES + 255) / 256)          // 391
#define HIST_BLOCKS ((N_EDGES / 4 + 255) / 256)      // 1563
#define FUSED_GRID  (GEMM_BLOCKS + HIST_BLOCKS)      // 1954

typedef unsigned long long u64;

// __device__ scratch (no allocs allowed). Zero-initialized at module load;
// g_count is re-zeroed by reduce_kernel at the end of every run so each
// replay starts from a clean histogram.
__device__ __half2 g_h2[(size_t)N_NODES * (D_OUT / 2)];  // 12.8 MB, fp16 h
__device__ int   g_count[N_NODES];
__device__ int   g_offset[N_NODES];
__device__ int   g_cursor[N_NODES];
__device__ int   g_src_sorted[N_EDGES];                  // 6.4 MB
__device__ int   g_blocksums[NBLK];

// ---------------------------------------------------------------------------
// packed f32x2 helpers (Blackwell FFMA2 path — only reachable via PTX)
// ---------------------------------------------------------------------------
__device__ __forceinline__ void ffma2(u64& d, u64 a, u64 b, u64 c) {
    asm("fma.rn.f32x2 %0, %1, %2, %3;" : "=l"(d) : "l"(a), "l"(b), "l"(c));
}
__device__ __forceinline__ u64 pack2(float lo, float hi) {
    u64 r;
    asm("mov.b64 %0, {%1, %2};" : "=l"(r) : "f"(lo), "f"(hi));
    return r;
}
__device__ __forceinline__ void unpack2(u64 v, float& lo, float& hi) {
    asm("mov.b64 {%0, %1}, %2;" : "=f"(lo), "=f"(hi) : "l"(v));
}

// ---------------------------------------------------------------------------
// Fused kernel: GEMM (h = x @ W) blocks interleaved with dst-histogram blocks.
// blockIdx % 5 == 0  -> GEMM block (391 of them)
// otherwise          -> histogram block (1563 of them, 4 edges/thread)
// The two block types are independent and stress different pipes (FMA vs LTS
// atomics), so they overlap instead of serializing as two launches.
// ---------------------------------------------------------------------------
__global__ __launch_bounds__(256, 2)
void gemm_hist_kernel(const float* __restrict__ x, const float* __restrict__ W,
                      const int* __restrict__ edge_index) {
    __shared__ u64 sW[D_IN][D_OUT / 2];   // 32 KB (unused by hist blocks)

    int g = blockIdx.x;
    int tid = threadIdx.x;

    if (g % 5 != 0) {
        // ---- histogram block ----
        int hb = g - (g / 5 + 1);              // 0 .. HIST_BLOCKS-1
        int i = hb * 256 + tid;                // int4 edge group index
        if (i < N_EDGES / 4) {
            int4 d = __ldg((const int4*)(edge_index + N_EDGES) + i);
            atomicAdd(&g_count[d.x], 1);
            atomicAdd(&g_count[d.y], 1);
            atomicAdd(&g_count[d.z], 1);
            atomicAdd(&g_count[d.w], 1);
        }
        return;
    }

    // ---- GEMM block ----
    int gb = g / 5;                            // 0 .. GEMM_BLOCKS-1

    const float4* W4 = (const float4*)W;
    #pragma unroll
    for (int i = tid; i < D_IN * D_OUT / 4; i += 256) {
        float4 v = W4[i];
        int k = i >> 4;
        int j = i & 15;
        sW[k][2 * j + 0] = pack2(v.x, v.y);
        sW[k][2 * j + 1] = pack2(v.z, v.w);
    }
    __syncthreads();

    int tx = tid & 3;
    int ty = tid >> 2;
    int m0 = gb * 256 + ty * 4;
    int j0 = tx * 8;

    u64 acc[4][8];
    #pragma unroll
    for (int r = 0; r < 4; r++)
        #pragma unroll
        for (int q = 0; q < 8; q++)
            acc[r][q] = 0ull;

    const float4* x4 = (const float4*)x;

    for (int k4 = 0; k4 < D_IN / 4; k4++) {
        float xs[4][4];
        #pragma unroll
        for (int r = 0; r < 4; r++) {
            int m = m0 + r;
            float4 v = (m < N_NODES) ? x4[(size_t)m * (D_IN / 4) + k4]
                                     : make_float4(0.f, 0.f, 0.f, 0.f);
            xs[r][0] = v.x; xs[r][1] = v.y; xs[r][2] = v.z; xs[r][3] = v.w;
        }
        #pragma unroll
        for (int kk = 0; kk < 4; kk++) {
            int k = k4 * 4 + kk;
            ulonglong2 wv[4];
            #pragma unroll
            for (int q = 0; q < 4; q++)
                wv[q] = *(ulonglong2*)&sW[k][j0 + 2 * q];
            u64 w[8];
            #pragma unroll
            for (int q = 0; q < 4; q++) { w[2*q] = wv[q].x; w[2*q+1] = wv[q].y; }
            #pragma unroll
            for (int r = 0; r < 4; r++) {
                u64 a2 = pack2(xs[r][kk], xs[r][kk]);
                #pragma unroll
                for (int q = 0; q < 8; q++)
                    ffma2(acc[r][q], a2, w[q], acc[r][q]);
            }
        }
    }

    #pragma unroll
    for (int r = 0; r < 4; r++) {
        int m = m0 + r;
        if (m < N_NODES) {
            uint4 st[2];
            unsigned* sp = (unsigned*)st;
            #pragma unroll
            for (int q = 0; q < 8; q++) {
                float lo, hi;
                unpack2(acc[r][q], lo, hi);
                __half2 hh = __floats2half2_rn(lo, hi);
                sp[q] = *(unsigned*)&hh;
            }
            uint4* hp = (uint4*)(g_h2 + (size_t)m * (D_OUT / 2) + tx * 8);
            hp[0] = st[0];
            hp[1] = st[1];
        }
    }
}

// ---------------------------------------------------------------------------
// scanA: per-block sums of counts (warp-shuffle reduction, 1 barrier)
// ---------------------------------------------------------------------------
__global__ __launch_bounds__(SCAN_BLK)
void scanA_kernel() {
    __shared__ int wsum[32];
    int tid  = threadIdx.x;
    int lane = tid & 31;
    int w    = tid >> 5;
    int i = blockIdx.x * SCAN_BLK + tid;
    int v = (i < N_NODES) ? g_count[i] : 0;
    #pragma unroll
    for (int st = 16; st > 0; st >>= 1)
        v += __shfl_down_sync(0xffffffffu, v, st);
    if (lane == 0) wsum[w] = v;
    __syncthreads();
    if (w == 0) {
        int s = wsum[lane];
        #pragma unroll
        for (int st = 16; st > 0; st >>= 1)
            s += __shfl_down_sync(0xffffffffu, s, st);
        if (lane == 0) g_blocksums[blockIdx.x] = s;
    }
}

// ---------------------------------------------------------------------------
// scanC: per-block exclusive scan via warp shuffles (2 barriers); warp 31
// concurrently computes this block's prefix over preceding block sums.
// ---------------------------------------------------------------------------
__global__ __launch_bounds__(SCAN_BLK)
void scanC_kernel() {
    __shared__ int wsum[32];
    __shared__ int s_prefix;
    int tid  = threadIdx.x;
    int lane = tid & 31;
    int w    = tid >> 5;

    if (w == 31) {
        int p = 0;
        for (int i = lane; i < blockIdx.x; i += 32) p += g_blocksums[i];
        #pragma unroll
        for (int st = 16; st > 0; st >>= 1)
            p += __shfl_down_sync(0xffffffffu, p, st);
        if (lane == 0) s_prefix = p;
    }

    int i = blockIdx.x * SCAN_BLK + tid;
    int v = (i < N_NODES) ? g_count[i] : 0;
    int s = v;
    #pragma unroll
    for (int st = 1; st < 32; st <<= 1) {
        int t = __shfl_up_sync(0xffffffffu, s, st);
        if (lane >= st) s += t;
    }
    if (lane == 31) wsum[w] = s;
    __syncthreads();
    if (w == 0) {
        int ws = wsum[lane];
        int t = ws;
        #pragma unroll
        for (int st = 1; st < 32; st <<= 1) {
            int u = __shfl_up_sync(0xffffffffu, t, st);
            if (lane >= st) t += u;
        }
        wsum[lane] = t - ws;   // exclusive
    }
    __syncthreads();
    if (i < N_NODES) {
        int excl = (s - v) + wsum[w] + s_prefix;
        g_offset[i] = excl;
        g_cursor[i] = excl;
    }
}

// ---------------------------------------------------------------------------
// bucket-scatter src indices into dst-sorted order (4 edges per thread)
// ---------------------------------------------------------------------------
__global__ void bucket_scatter_kernel(const int* __restrict__ edge_index) {
    int i = blockIdx.x * blockDim.x + threadIdx.x;
    if (i >= N_EDGES / 4) return;
    int4 s = __ldg((const int4*)edge_index + i);
    int4 d = __ldg((const int4*)(edge_index + N_EDGES) + i);
    g_src_sorted[atomicAdd(&g_cursor[d.x], 1)] = s.x;
    g_src_sorted[atomicAdd(&g_cursor[d.y], 1)] = s.y;
    g_src_sorted[atomicAdd(&g_cursor[d.z], 1)] = s.z;
    g_src_sorted[atomicAdd(&g_cursor[d.w], 1)] = s.w;
}

// ---------------------------------------------------------------------------
// Reduce: one warp per dst node. One coalesced 128B request per edge row.
// fp32 accumulation, relu(acc+b), single write. Re-zeroes g_count[n] after
// the final read so the next replay starts from a clean histogram.
// ---------------------------------------------------------------------------
__global__ __launch_bounds__(256)
void reduce_kernel(float* __restrict__ out, const float* __restrict__ b) {
    int warp = threadIdx.x >> 5;
    int lane = threadIdx.x & 31;
    int n = blockIdx.x * 8 + warp;
    if (n >= N_NODES) return;

    int start = g_offset[n];
    int cnt   = g_count[n];
    if (lane == 0) g_count[n] = 0;      // reset for next run

    float a0 = 0.f, a1 = 0.f;
    for (int base = 0; base < cnt; base += 32) {
        int my = 0;
        if (base + lane < cnt) my = __ldg(&g_src_sorted[start + base + lane]);
        int m = min(32, cnt - base);
        #pragma unroll 8
        for (int j = 0; j < m; j++) {
            int src = __shfl_sync(0xffffffffu, my, j);
            __half2 v = __ldg(g_h2 + (size_t)src * (D_OUT / 2) + lane);
            float2 f = __half22float2(v);
            a0 += f.x;
            a1 += f.y;
        }
    }
    a0 = fmaxf(a0 + __ldg(b + 2 * lane),     0.f);
    a1 = fmaxf(a1 + __ldg(b + 2 * lane + 1), 0.f);
    float2 o; o.x = a0; o.y = a1;
    ((float2*)(out + (size_t)n * D_OUT))[lane] = o;
}

// ---------------------------------------------------------------------------
extern "C" void kernel_launch(void* const* d_in, const int* in_sizes, int n_in,
                              void* d_out, int out_size) {
    const float* x          = (const float*)d_in[0];   // [100000, 128]
    const int*   edge_index = (const int*)d_in[1];     // [2, 1600000]
    const float* W          = (const float*)d_in[2];   // [128, 64]
    const float* b          = (const float*)d_in[3];   // [64]
    float*       out        = (float*)d_out;           // [100000, 64]

    // GEMM + dst histogram, overlapped in one launch
    gemm_hist_kernel<<<FUSED_GRID, 256>>>(x, W, edge_index);

    // exclusive scan of counts -> offsets & cursors
    scanA_kernel<<<NBLK, SCAN_BLK>>>();
    scanC_kernel<<<NBLK, SCAN_BLK>>>();

    // dst-sorted src list
    bucket_scatter_kernel<<<(N_EDGES / 4 + 255) / 256, 256>>>(edge_index);

    // gather-reduce + bias + relu (one warp per node); resets g_count
    reduce_kernel<<<(N_NODES + 7) / 8, 256>>>(out, b);
}

// round 13
// speedup vs baseline: 1.5974x; 1.5974x over previous
#include <cuda_runtime.h>
#include <cuda_fp16.h>
#include <cuda_bf16.h>

#define N_NODES 100000
#define N_EDGES 1600000
#define D_IN    128
#define D_OUT   64
#define SCAN_BLK 1024
#define NBLK ((N_NODES + SCAN_BLK - 1) / SCAN_BLK)   // 98

typedef unsigned long long u64;

// __device__ scratch (no allocs allowed)
__device__ __half2 g_h2[(size_t)N_NODES * (D_OUT / 2)];  // 12.8 MB, fp16 h
__device__ int   g_count[N_NODES];
__device__ int   g_offset[N_NODES];
__device__ int   g_cursor[N_NODES];
__device__ int   g_src_sorted[N_EDGES];                  // 6.4 MB
__device__ int   g_blocksums[NBLK];

// ---------------------------------------------------------------------------
// packed f32x2 helpers (Blackwell FFMA2 path — only reachable via PTX)
// ---------------------------------------------------------------------------
__device__ __forceinline__ void ffma2(u64& d, u64 a, u64 b, u64 c) {
    asm("fma.rn.f32x2 %0, %1, %2, %3;" : "=l"(d) : "l"(a), "l"(b), "l"(c));
}
__device__ __forceinline__ u64 pack2(float lo, float hi) {
    u64 r;
    asm("mov.b64 %0, {%1, %2};" : "=l"(r) : "f"(lo), "f"(hi));
    return r;
}
__device__ __forceinline__ void unpack2(u64 v, float& lo, float& hi) {
    asm("mov.b64 {%0, %1}, %2;" : "=f"(lo), "=f"(hi) : "l"(v));
}

// ---------------------------------------------------------------------------
// GEMM: h = x @ W, packed f32x2 FMA, fp16 store. Also zeroes g_count
// (histogram) as a side job — runs before hist in the serial graph.
// ---------------------------------------------------------------------------
__global__ __launch_bounds__(256, 2)
void gemm_kernel(const float* __restrict__ x, const float* __restrict__ W) {
    // side job: zero the dst histogram (25000 int4 slots)
    {
        int idx = blockIdx.x * 256 + threadIdx.x;
        if (idx < N_NODES / 4)
            ((int4*)g_count)[idx] = make_int4(0, 0, 0, 0);
    }

    __shared__ u64 sW[D_IN][D_OUT / 2];   // 32 KB

    int tid = threadIdx.x;
    const float4* W4 = (const float4*)W;
    #pragma unroll
    for (int i = tid; i < D_IN * D_OUT / 4; i += 256) {
        float4 v = W4[i];
        int k = i >> 4;
        int j = i & 15;
        sW[k][2 * j + 0] = pack2(v.x, v.y);
        sW[k][2 * j + 1] = pack2(v.z, v.w);
    }
    __syncthreads();

    int tx = tid & 3;
    int ty = tid >> 2;
    int m0 = blockIdx.x * 256 + ty * 4;
    int j0 = tx * 8;

    u64 acc[4][8];
    #pragma unroll
    for (int r = 0; r < 4; r++)
        #pragma unroll
        for (int q = 0; q < 8; q++)
            acc[r][q] = 0ull;

    const float4* x4 = (const float4*)x;

    for (int k4 = 0; k4 < D_IN / 4; k4++) {
        float xs[4][4];
        #pragma unroll
        for (int r = 0; r < 4; r++) {
            int m = m0 + r;
            float4 v = (m < N_NODES) ? x4[(size_t)m * (D_IN / 4) + k4]
                                     : make_float4(0.f, 0.f, 0.f, 0.f);
            xs[r][0] = v.x; xs[r][1] = v.y; xs[r][2] = v.z; xs[r][3] = v.w;
        }
        #pragma unroll
        for (int kk = 0; kk < 4; kk++) {
            int k = k4 * 4 + kk;
            ulonglong2 wv[4];
            #pragma unroll
            for (int q = 0; q < 4; q++)
                wv[q] = *(ulonglong2*)&sW[k][j0 + 2 * q];
            u64 w[8];
            #pragma unroll
            for (int q = 0; q < 4; q++) { w[2*q] = wv[q].x; w[2*q+1] = wv[q].y; }
            #pragma unroll
            for (int r = 0; r < 4; r++) {
                u64 a2 = pack2(xs[r][kk], xs[r][kk]);
                #pragma unroll
                for (int q = 0; q < 8; q++)
                    ffma2(acc[r][q], a2, w[q], acc[r][q]);
            }
        }
    }

    #pragma unroll
    for (int r = 0; r < 4; r++) {
        int m = m0 + r;
        if (m < N_NODES) {
            uint4 st[2];
            unsigned* sp = (unsigned*)st;
            #pragma unroll
            for (int q = 0; q < 8; q++) {
                float lo, hi;
                unpack2(acc[r][q], lo, hi);
                __half2 hh = __floats2half2_rn(lo, hi);
                sp[q] = *(unsigned*)&hh;
            }
            uint4* hp = (uint4*)(g_h2 + (size_t)m * (D_OUT / 2) + tx * 8);
            hp[0] = st[0];
            hp[1] = st[1];
        }
    }
}

// ---------------------------------------------------------------------------
// histogram of dst (4 edges per thread)
// ---------------------------------------------------------------------------
__global__ void hist_kernel(const int* __restrict__ edge_index) {
    int i = blockIdx.x * blockDim.x + threadIdx.x;
    if (i >= N_EDGES / 4) return;
    int4 d = __ldg((const int4*)(edge_index + N_EDGES) + i);
    atomicAdd(&g_count[d.x], 1);
    atomicAdd(&g_count[d.y], 1);
    atomicAdd(&g_count[d.z], 1);
    atomicAdd(&g_count[d.w], 1);
}

// ---------------------------------------------------------------------------
// scanA: per-block sums of counts (warp-shuffle reduction, 1 barrier)
// ---------------------------------------------------------------------------
__global__ __launch_bounds__(SCAN_BLK)
void scanA_kernel() {
    __shared__ int wsum[32];
    int tid  = threadIdx.x;
    int lane = tid & 31;
    int w    = tid >> 5;
    int i = blockIdx.x * SCAN_BLK + tid;
    int v = (i < N_NODES) ? g_count[i] : 0;
    #pragma unroll
    for (int st = 16; st > 0; st >>= 1)
        v += __shfl_down_sync(0xffffffffu, v, st);
    if (lane == 0) wsum[w] = v;
    __syncthreads();
    if (w == 0) {
        int s = wsum[lane];
        #pragma unroll
        for (int st = 16; st > 0; st >>= 1)
            s += __shfl_down_sync(0xffffffffu, s, st);
        if (lane == 0) g_blocksums[blockIdx.x] = s;
    }
}

// ---------------------------------------------------------------------------
// scanC: per-block exclusive scan via warp shuffles (2 barriers); warp 31
// concurrently computes this block's prefix over preceding block sums.
// ---------------------------------------------------------------------------
__global__ __launch_bounds__(SCAN_BLK)
void scanC_kernel() {
    __shared__ int wsum[32];
    __shared__ int s_prefix;
    int tid  = threadIdx.x;
    int lane = tid & 31;
    int w    = tid >> 5;

    if (w == 31) {
        int p = 0;
        for (int i = lane; i < blockIdx.x; i += 32) p += g_blocksums[i];
        #pragma unroll
        for (int st = 16; st > 0; st >>= 1)
            p += __shfl_down_sync(0xffffffffu, p, st);
        if (lane == 0) s_prefix = p;
    }

    int i = blockIdx.x * SCAN_BLK + tid;
    int v = (i < N_NODES) ? g_count[i] : 0;
    int s = v;
    #pragma unroll
    for (int st = 1; st < 32; st <<= 1) {
        int t = __shfl_up_sync(0xffffffffu, s, st);
        if (lane >= st) s += t;
    }
    if (lane == 31) wsum[w] = s;
    __syncthreads();
    if (w == 0) {
        int ws = wsum[lane];
        int t = ws;
        #pragma unroll
        for (int st = 1; st < 32; st <<= 1) {
            int u = __shfl_up_sync(0xffffffffu, t, st);
            if (lane >= st) t += u;
        }
        wsum[lane] = t - ws;   // exclusive
    }
    __syncthreads();
    if (i < N_NODES) {
        int excl = (s - v) + wsum[w] + s_prefix;
        g_offset[i] = excl;
        g_cursor[i] = excl;
    }
}

// ---------------------------------------------------------------------------
// bucket-scatter src indices into dst-sorted order (4 edges per thread)
// ---------------------------------------------------------------------------
__global__ void bucket_scatter_kernel(const int* __restrict__ edge_index) {
    int i = blockIdx.x * blockDim.x + threadIdx.x;
    if (i >= N_EDGES / 4) return;
    int4 s = __ldg((const int4*)edge_index + i);
    int4 d = __ldg((const int4*)(edge_index + N_EDGES) + i);
    g_src_sorted[atomicAdd(&g_cursor[d.x], 1)] = s.x;
    g_src_sorted[atomicAdd(&g_cursor[d.y], 1)] = s.y;
    g_src_sorted[atomicAdd(&g_cursor[d.z], 1)] = s.z;
    g_src_sorted[atomicAdd(&g_cursor[d.w], 1)] = s.w;
}

// ---------------------------------------------------------------------------
// Reduce: one warp per dst node. One coalesced 128B request per edge row
// (4B half2 per lane). fp32 accumulation, relu(acc+b), single write.
// ---------------------------------------------------------------------------
__global__ __launch_bounds__(256)
void reduce_kernel(float* __restrict__ out, const float* __restrict__ b) {
    int warp = threadIdx.x >> 5;
    int lane = threadIdx.x & 31;
    int n = blockIdx.x * 8 + warp;
    if (n >= N_NODES) return;

    int start = g_offset[n];
    int cnt   = g_count[n];

    float a0 = 0.f, a1 = 0.f;
    for (int base = 0; base < cnt; base += 32) {
        int my = 0;
        if (base + lane < cnt) my = __ldg(&g_src_sorted[start + base + lane]);
        int m = min(32, cnt - base);
        #pragma unroll 8
        for (int j = 0; j < m; j++) {
            int src = __shfl_sync(0xffffffffu, my, j);
            __half2 v = __ldg(g_h2 + (size_t)src * (D_OUT / 2) + lane);
            float2 f = __half22float2(v);
            a0 += f.x;
            a1 += f.y;
        }
    }
    a0 = fmaxf(a0 + __ldg(b + 2 * lane),     0.f);
    a1 = fmaxf(a1 + __ldg(b + 2 * lane + 1), 0.f);
    float2 o; o.x = a0; o.y = a1;
    ((float2*)(out + (size_t)n * D_OUT))[lane] = o;
}

// ---------------------------------------------------------------------------
extern "C" void kernel_launch(void* const* d_in, const int* in_sizes, int n_in,
                              void* d_out, int out_size) {
    const float* x          = (const float*)d_in[0];   // [100000, 128]
    const int*   edge_index = (const int*)d_in[1];     // [2, 1600000]
    const float* W          = (const float*)d_in[2];   // [128, 64]
    const float* b          = (const float*)d_in[3];   // [64]
    float*       out        = (float*)d_out;           // [100000, 64]

    // h = x @ W (packed f32x2 FMA, fp16 store) + zero histogram
    gemm_kernel<<<(N_NODES + 255) / 256, 256>>>(x, W);

    // counting sort of edges by dst
    hist_kernel<<<(N_EDGES / 4 + 255) / 256, 256>>>(edge_index);
    scanA_kernel<<<NBLK, SCAN_BLK>>>();
    scanC_kernel<<<NBLK, SCAN_BLK>>>();
    bucket_scatter_kernel<<<(N_EDGES / 4 + 255) / 256, 256>>>(edge_index);

    // gather-reduce + bias + relu (one warp per node)
    reduce_kernel<<<(N_NODES + 7) / 8, 256>>>(out, b);
}